// round 14
// baseline (speedup 1.0000x reference)
#include <cuda_runtime.h>

// JPEG encode: (512,3,128,128) fp32 -> -128 -> 8x8 DCT -> quant -> zigzag
// out = [flatten (256,512,192) | no_quan_flatten (256,512,192)] fp32
//
// R13 = R12 with a legal evict_last encoding: sm_103a requires 256-bit loads
// for L2::evict_last, and each block row is exactly 32B/32B-aligned -> one
// ld.global.nc.L2::evict_last.v4.b64 per row (also halves LDG count).
//   input  : evict_last  (100MB replay-invariant read set, fits 126MB L2)
//   output : __stcs evict-first (201MB write stream passes through)

#define BT 128
#define STRIDE 68   // floats; 272B slot pitch -> conflict-free 16B ld/st

// 0.5*cos(k*pi/16)
#define C1f 0.49039264020161522f
#define C2f 0.46193976625564338f
#define C3f 0.41573480615127262f
#define C4f 0.35355339059327376f
#define C5f 0.27778511650980111f
#define C6f 0.19134171618254489f
#define C7f 0.09754516100806413f

// D[j][k] for k=0..3 (k=4..7 follow by even/odd symmetry)
__device__ constexpr float DCm[8][4] = {
    { C4f,  C4f,  C4f,  C4f},
    { C1f,  C3f,  C5f,  C7f},
    { C2f,  C6f, -C6f, -C2f},
    { C3f, -C7f, -C1f, -C5f},
    { C4f, -C4f, -C4f,  C4f},
    { C5f, -C1f,  C7f,  C3f},
    { C6f, -C2f,  C2f, -C6f},
    { C7f, -C5f,  C3f, -C1f}};

__constant__ int c_zz[64] = {  // zigzag position p reads flat index zz[p]
     0,  1,  8, 16,  9,  2,  3, 10,
    17, 24, 32, 25, 18, 11,  4,  5,
    12, 19, 26, 33, 40, 48, 41, 34,
    27, 20, 13,  6,  7, 14, 21, 28,
    35, 42, 49, 56, 57, 50, 43, 36,
    29, 22, 15, 23, 30, 37, 44, 51,
    58, 59, 52, 45, 38, 31, 39, 46,
    53, 60, 61, 54, 47, 55, 62, 63};

// inverse zigzag: flat (i*8+j) lands at zigzag position INVZ[i*8+j]
__device__ constexpr int INVZ[64] = {
     0,  1,  5,  6, 14, 15, 27, 28,
     2,  4,  7, 13, 16, 26, 29, 42,
     3,  8, 12, 17, 25, 30, 41, 43,
     9, 11, 18, 24, 31, 40, 44, 53,
    10, 19, 23, 32, 39, 45, 52, 54,
    20, 22, 33, 38, 46, 51, 55, 60,
    21, 34, 37, 47, 50, 56, 59, 61,
    35, 36, 48, 49, 57, 58, 62, 63};

// One full 32B block-row load, L2 evict_last (retain across graph replays).
// sm_103a: evict_last needs a 256-bit load -> .v4.b64.
__device__ __forceinline__ void ldg_row_keep(const float* p, float x[8])
{
    unsigned long long r0, r1, r2, r3;
    asm volatile("ld.global.nc.L2::evict_last.v4.b64 {%0,%1,%2,%3}, [%4];"
                 : "=l"(r0), "=l"(r1), "=l"(r2), "=l"(r3)
                 : "l"(p));
    float2 f0 = *(float2*)&r0, f1 = *(float2*)&r1;
    float2 f2 = *(float2*)&r2, f3 = *(float2*)&r3;
    x[0] = f0.x; x[1] = f0.y; x[2] = f1.x; x[3] = f1.y;
    x[4] = f2.x; x[5] = f2.y; x[6] = f3.x; x[7] = f3.y;
}

// Row DCT of one image row via even/odd butterfly
__device__ __forceinline__ void row_dct(const float* __restrict__ rsrc, float T[8])
{
    float x[8];
    ldg_row_keep(rsrc, x);
    float e0 = x[0] + x[7], e1 = x[1] + x[6], e2 = x[2] + x[5], e3 = x[3] + x[4];
    float o0 = x[0] - x[7], o1 = x[1] - x[6], o2 = x[2] - x[5], o3 = x[3] - x[4];
#pragma unroll
    for (int j = 0; j < 8; j += 2) {
        T[j]   = fmaf(e3, DCm[j][3],   fmaf(e2, DCm[j][2],   fmaf(e1, DCm[j][1],   e0 * DCm[j][0])));
        T[j+1] = fmaf(o3, DCm[j+1][3], fmaf(o2, DCm[j+1][2], fmaf(o1, DCm[j+1][1], o0 * DCm[j+1][0])));
    }
}

__global__ __launch_bounds__(BT, 5)
void jpeg_encode_kernel(const float* __restrict__ img,
                        const float* __restrict__ Qm,
                        float* __restrict__ out_q,
                        float* __restrict__ out_nq)
{
    __shared__ float Qinv[64];             // 1/Q in zigzag order
    __shared__ float stage[BT * STRIDE];   // full stage: one slot per thread

    const int tid = threadIdx.x;
    if (tid < 64) Qinv[tid] = 1.0f / Qm[c_zz[tid]];

    // CTA = (nh, group of 8 planes); thread = (plane-in-group, nw)
    const int bid = blockIdx.x;            // 0..3071
    const int nh  = bid / 192;             // block-row 0..15
    const int bcg = bid % 192;             // plane group (8 planes each)
    const int bc  = bcg * 8 + (tid >> 4);  // plane = b*3+c
    const int nw  = tid & 15;              // block-col

    // img (B,C,128,128): plane stride 16384 floats, row stride 128
    const float* src = img + ((size_t)bc << 14) + (size_t)nh * 1024 + (size_t)nw * 8;

    // ---- 2D DCT, butterfly both passes, zigzag-renamed accumulators
    float Yz[64];
#pragma unroll
    for (int p = 0; p < 64; ++p) Yz[p] = 0.f;

#pragma unroll
    for (int rp = 0; rp < 4; ++rp) {       // row pair (rp, 7-rp)
        float Ta[8], Tb[8];
        row_dct(src + rp * 128,       Ta);
        row_dct(src + (7 - rp) * 128, Tb);
#pragma unroll
        for (int j = 0; j < 8; ++j) {
            float s = Ta[j] + Tb[j];       // feeds even output rows
            float d = Ta[j] - Tb[j];       // feeds odd output rows
#pragma unroll
            for (int h = 0; h < 4; ++h) {
                Yz[INVZ[(2*h)    *8 + j]] = fmaf(s, DCm[2*h][rp],     Yz[INVZ[(2*h)    *8 + j]]);
                Yz[INVZ[(2*h + 1)*8 + j]] = fmaf(d, DCm[2*h + 1][rp], Yz[INVZ[(2*h + 1)*8 + j]]);
            }
        }
    }
    // fold the (x - 128) bias: only the DC coefficient is affected
    Yz[0] -= 1024.0f;                      // INVZ[0] == 0

    // ---- stage (zigzag-ordered): 16 conflict-free STS.128
    float* st = stage + tid * STRIDE;
#pragma unroll
    for (int k = 0; k < 16; ++k)
        *(float4*)(st + 4 * k) =
            make_float4(Yz[4*k], Yz[4*k + 1], Yz[4*k + 2], Yz[4*k + 3]);
    __syncthreads();

    // ---- coalesced evict-first writes: 16 regions of 2KB, both tensors
    const size_t obase = (size_t)nh * (16 * 98304) + (size_t)bcg * 512 + tid * 4;
    const int slotbase = (tid >> 4) * 16;      // stage slot = bcl*16 + it
    const int pos      = (tid & 15) * 4;       // zigzag pos within block
    const float4 qv    = *(const float4*)(Qinv + pos);
#pragma unroll
    for (int it = 0; it < 16; ++it) {
        float4 v = *(const float4*)(stage + (slotbase + it) * STRIDE + pos);
        float4 q = make_float4(rintf(v.x * qv.x), rintf(v.y * qv.y),
                               rintf(v.z * qv.z), rintf(v.w * qv.w));
        const size_t o = obase + (size_t)it * 98304;
        __stcs((float4*)(out_nq + o), v);
        __stcs((float4*)(out_q  + o), q);
    }
}

extern "C" void kernel_launch(void* const* d_in, const int* in_sizes, int n_in,
                              void* d_out, int out_size)
{
    const float* img = (const float*)d_in[0];   // (512,3,128,128) fp32
    const float* Qm  = (const float*)d_in[2];   // (8,8) fp32
    float* out = (float*)d_out;

    const size_t half = (size_t)out_size / 2;   // flatten | no_quan_flatten
    jpeg_encode_kernel<<<3072, BT>>>(img, Qm, out, out + half);
}

// round 15
// speedup vs baseline: 1.0061x; 1.0061x over previous
#include <cuda_runtime.h>

// JPEG encode: (512,3,128,128) fp32 -> -128 -> 8x8 DCT -> quant -> zigzag
// out = [flatten (256,512,192) | no_quan_flatten (256,512,192)] fp32
//
// FINAL (= R3, best measured: dur 51.94us, kernel 46.0us):
//  - CTA = (block-row nh, group of 8 planes); half-warp sweeps a contiguous
//    512B image row -> near-ideal read coalescing for 8x8-block access
//  - butterfly 8-pt DCT both passes, coefficients baked as FFMA immediates
//  - (x-128) bias folded into the DC coefficient (exact for AC terms)
//  - zigzag via compile-time register renaming (free)
//  - one-pass smem stage (stride-68 slots, conflict-free 16B ld/st), then
//    fully-coalesced float4 stores of both output tensors
//  - launch_bounds(128,5): 96 regs preserves per-warp LDG batching (MLP);
//    all reg-cap/occupancy probes measured worse (R5/R6/R7)
// Steady-state: 302MB/iter / 46.7us = 6.47TB/s = ~81% of spec = HBM roofline.
// Neutral probes: __ldcs/__stcs, cp.async, __ldcg, L2::evict_last+LDG.256.

#define BT 128
#define STRIDE 68   // floats; 272B slot pitch -> conflict-free 16B ld/st

// 0.5*cos(k*pi/16)
#define C1f 0.49039264020161522f
#define C2f 0.46193976625564338f
#define C3f 0.41573480615127262f
#define C4f 0.35355339059327376f
#define C5f 0.27778511650980111f
#define C6f 0.19134171618254489f
#define C7f 0.09754516100806413f

// D[j][k] for k=0..3 (k=4..7 follow by even/odd symmetry)
__device__ constexpr float DCm[8][4] = {
    { C4f,  C4f,  C4f,  C4f},
    { C1f,  C3f,  C5f,  C7f},
    { C2f,  C6f, -C6f, -C2f},
    { C3f, -C7f, -C1f, -C5f},
    { C4f, -C4f, -C4f,  C4f},
    { C5f, -C1f,  C7f,  C3f},
    { C6f, -C2f,  C2f, -C6f},
    { C7f, -C5f,  C3f, -C1f}};

__constant__ int c_zz[64] = {  // zigzag position p reads flat index zz[p]
     0,  1,  8, 16,  9,  2,  3, 10,
    17, 24, 32, 25, 18, 11,  4,  5,
    12, 19, 26, 33, 40, 48, 41, 34,
    27, 20, 13,  6,  7, 14, 21, 28,
    35, 42, 49, 56, 57, 50, 43, 36,
    29, 22, 15, 23, 30, 37, 44, 51,
    58, 59, 52, 45, 38, 31, 39, 46,
    53, 60, 61, 54, 47, 55, 62, 63};

// inverse zigzag: flat (i*8+j) lands at zigzag position INVZ[i*8+j]
__device__ constexpr int INVZ[64] = {
     0,  1,  5,  6, 14, 15, 27, 28,
     2,  4,  7, 13, 16, 26, 29, 42,
     3,  8, 12, 17, 25, 30, 41, 43,
     9, 11, 18, 24, 31, 40, 44, 53,
    10, 19, 23, 32, 39, 45, 52, 54,
    20, 22, 33, 38, 46, 51, 55, 60,
    21, 34, 37, 47, 50, 56, 59, 61,
    35, 36, 48, 49, 57, 58, 62, 63};

// Row DCT of one image row via even/odd butterfly
__device__ __forceinline__ void row_dct(const float* __restrict__ rsrc, float T[8])
{
    float4 a = *(const float4*)rsrc;
    float4 b = *(const float4*)(rsrc + 4);
    float e0 = a.x + b.w, e1 = a.y + b.z, e2 = a.z + b.y, e3 = a.w + b.x;
    float o0 = a.x - b.w, o1 = a.y - b.z, o2 = a.z - b.y, o3 = a.w - b.x;
#pragma unroll
    for (int j = 0; j < 8; j += 2) {
        T[j]   = fmaf(e3, DCm[j][3],   fmaf(e2, DCm[j][2],   fmaf(e1, DCm[j][1],   e0 * DCm[j][0])));
        T[j+1] = fmaf(o3, DCm[j+1][3], fmaf(o2, DCm[j+1][2], fmaf(o1, DCm[j+1][1], o0 * DCm[j+1][0])));
    }
}

__global__ __launch_bounds__(BT, 5)
void jpeg_encode_kernel(const float* __restrict__ img,
                        const float* __restrict__ Qm,
                        float* __restrict__ out_q,
                        float* __restrict__ out_nq)
{
    __shared__ float Qinv[64];             // 1/Q in zigzag order
    __shared__ float stage[BT * STRIDE];   // full stage: one slot per thread

    const int tid = threadIdx.x;
    if (tid < 64) Qinv[tid] = 1.0f / Qm[c_zz[tid]];

    // CTA = (nh, group of 8 planes); thread = (plane-in-group, nw)
    const int bid = blockIdx.x;            // 0..3071
    const int nh  = bid / 192;             // block-row 0..15
    const int bcg = bid % 192;             // plane group (8 planes each)
    const int bc  = bcg * 8 + (tid >> 4);  // plane = b*3+c
    const int nw  = tid & 15;              // block-col

    // img (B,C,128,128): plane stride 16384 floats, row stride 128
    const float* src = img + ((size_t)bc << 14) + (size_t)nh * 1024 + (size_t)nw * 8;

    // ---- 2D DCT, butterfly both passes, zigzag-renamed accumulators
    float Yz[64];
#pragma unroll
    for (int p = 0; p < 64; ++p) Yz[p] = 0.f;

#pragma unroll
    for (int rp = 0; rp < 4; ++rp) {       // row pair (rp, 7-rp)
        float Ta[8], Tb[8];
        row_dct(src + rp * 128,       Ta);
        row_dct(src + (7 - rp) * 128, Tb);
#pragma unroll
        for (int j = 0; j < 8; ++j) {
            float s = Ta[j] + Tb[j];       // feeds even output rows
            float d = Ta[j] - Tb[j];       // feeds odd output rows
#pragma unroll
            for (int h = 0; h < 4; ++h) {
                Yz[INVZ[(2*h)    *8 + j]] = fmaf(s, DCm[2*h][rp],     Yz[INVZ[(2*h)    *8 + j]]);
                Yz[INVZ[(2*h + 1)*8 + j]] = fmaf(d, DCm[2*h + 1][rp], Yz[INVZ[(2*h + 1)*8 + j]]);
            }
        }
    }
    // fold the (x - 128) bias: only the DC coefficient is affected
    Yz[0] -= 1024.0f;                      // INVZ[0] == 0

    // ---- stage (zigzag-ordered): 16 conflict-free STS.128
    float* st = stage + tid * STRIDE;
#pragma unroll
    for (int k = 0; k < 16; ++k)
        *(float4*)(st + 4 * k) =
            make_float4(Yz[4*k], Yz[4*k + 1], Yz[4*k + 2], Yz[4*k + 3]);
    __syncthreads();

    // ---- coalesced writes: 16 regions of 2KB (one per nw), both tensors
    const size_t obase = (size_t)nh * (16 * 98304) + (size_t)bcg * 512 + tid * 4;
    const int slotbase = (tid >> 4) * 16;      // stage slot = bcl*16 + it
    const int pos      = (tid & 15) * 4;       // zigzag pos within block
    const float4 qv    = *(const float4*)(Qinv + pos);
#pragma unroll
    for (int it = 0; it < 16; ++it) {
        float4 v = *(const float4*)(stage + (slotbase + it) * STRIDE + pos);
        float4 q = make_float4(rintf(v.x * qv.x), rintf(v.y * qv.y),
                               rintf(v.z * qv.z), rintf(v.w * qv.w));
        const size_t o = obase + (size_t)it * 98304;
        *(float4*)(out_nq + o) = v;
        *(float4*)(out_q  + o) = q;
    }
}

extern "C" void kernel_launch(void* const* d_in, const int* in_sizes, int n_in,
                              void* d_out, int out_size)
{
    const float* img = (const float*)d_in[0];   // (512,3,128,128) fp32
    const float* Qm  = (const float*)d_in[2];   // (8,8) fp32
    float* out = (float*)d_out;

    const size_t half = (size_t)out_size / 2;   // flatten | no_quan_flatten
    jpeg_encode_kernel<<<3072, BT>>>(img, Qm, out, out + half);
}

// round 16
// speedup vs baseline: 1.0122x; 1.0061x over previous
#include <cuda_runtime.h>

// JPEG encode: (512,3,128,128) fp32 -> -128 -> 8x8 DCT -> quant -> zigzag
// out = [flatten (256,512,192) | no_quan_flatten (256,512,192)] fp32
//
// FINAL (best measured: dur 51.94us, kernel 46.0us; reconfirmed x3):
//  - CTA = (block-row nh, group of 8 planes); half-warp sweeps a contiguous
//    512B image row -> near-ideal read coalescing for 8x8-block access
//  - butterfly 8-pt DCT both passes, coefficients baked as FFMA immediates
//  - (x-128) bias folded into the DC coefficient (exact for AC terms)
//  - zigzag via compile-time register renaming (free)
//  - one-pass smem stage (stride-68 slots, conflict-free 16B ld/st), then
//    fully-coalesced float4 stores of both output tensors
//  - launch_bounds(128,5): 96 regs preserves per-warp LDG batching (MLP);
//    all reg-cap/occupancy probes measured worse (R5/R6/R7)
// Steady-state: 302MB/iter / 46.0us = 6.56TB/s = ~82% of spec = HBM roofline.
// Neutral probes: __ldcs/__stcs, cp.async, __ldcg, L2::evict_last+LDG.256.
// Regressed probes: 2-tile CTA, 2-pass stage, reg caps (MLP loss / spill).

#define BT 128
#define STRIDE 68   // floats; 272B slot pitch -> conflict-free 16B ld/st

// 0.5*cos(k*pi/16)
#define C1f 0.49039264020161522f
#define C2f 0.46193976625564338f
#define C3f 0.41573480615127262f
#define C4f 0.35355339059327376f
#define C5f 0.27778511650980111f
#define C6f 0.19134171618254489f
#define C7f 0.09754516100806413f

// D[j][k] for k=0..3 (k=4..7 follow by even/odd symmetry)
__device__ constexpr float DCm[8][4] = {
    { C4f,  C4f,  C4f,  C4f},
    { C1f,  C3f,  C5f,  C7f},
    { C2f,  C6f, -C6f, -C2f},
    { C3f, -C7f, -C1f, -C5f},
    { C4f, -C4f, -C4f,  C4f},
    { C5f, -C1f,  C7f,  C3f},
    { C6f, -C2f,  C2f, -C6f},
    { C7f, -C5f,  C3f, -C1f}};

__constant__ int c_zz[64] = {  // zigzag position p reads flat index zz[p]
     0,  1,  8, 16,  9,  2,  3, 10,
    17, 24, 32, 25, 18, 11,  4,  5,
    12, 19, 26, 33, 40, 48, 41, 34,
    27, 20, 13,  6,  7, 14, 21, 28,
    35, 42, 49, 56, 57, 50, 43, 36,
    29, 22, 15, 23, 30, 37, 44, 51,
    58, 59, 52, 45, 38, 31, 39, 46,
    53, 60, 61, 54, 47, 55, 62, 63};

// inverse zigzag: flat (i*8+j) lands at zigzag position INVZ[i*8+j]
__device__ constexpr int INVZ[64] = {
     0,  1,  5,  6, 14, 15, 27, 28,
     2,  4,  7, 13, 16, 26, 29, 42,
     3,  8, 12, 17, 25, 30, 41, 43,
     9, 11, 18, 24, 31, 40, 44, 53,
    10, 19, 23, 32, 39, 45, 52, 54,
    20, 22, 33, 38, 46, 51, 55, 60,
    21, 34, 37, 47, 50, 56, 59, 61,
    35, 36, 48, 49, 57, 58, 62, 63};

// Row DCT of one image row via even/odd butterfly
__device__ __forceinline__ void row_dct(const float* __restrict__ rsrc, float T[8])
{
    float4 a = *(const float4*)rsrc;
    float4 b = *(const float4*)(rsrc + 4);
    float e0 = a.x + b.w, e1 = a.y + b.z, e2 = a.z + b.y, e3 = a.w + b.x;
    float o0 = a.x - b.w, o1 = a.y - b.z, o2 = a.z - b.y, o3 = a.w - b.x;
#pragma unroll
    for (int j = 0; j < 8; j += 2) {
        T[j]   = fmaf(e3, DCm[j][3],   fmaf(e2, DCm[j][2],   fmaf(e1, DCm[j][1],   e0 * DCm[j][0])));
        T[j+1] = fmaf(o3, DCm[j+1][3], fmaf(o2, DCm[j+1][2], fmaf(o1, DCm[j+1][1], o0 * DCm[j+1][0])));
    }
}

__global__ __launch_bounds__(BT, 5)
void jpeg_encode_kernel(const float* __restrict__ img,
                        const float* __restrict__ Qm,
                        float* __restrict__ out_q,
                        float* __restrict__ out_nq)
{
    __shared__ float Qinv[64];             // 1/Q in zigzag order
    __shared__ float stage[BT * STRIDE];   // full stage: one slot per thread

    const int tid = threadIdx.x;
    if (tid < 64) Qinv[tid] = 1.0f / Qm[c_zz[tid]];

    // CTA = (nh, group of 8 planes); thread = (plane-in-group, nw)
    const int bid = blockIdx.x;            // 0..3071
    const int nh  = bid / 192;             // block-row 0..15
    const int bcg = bid % 192;             // plane group (8 planes each)
    const int bc  = bcg * 8 + (tid >> 4);  // plane = b*3+c
    const int nw  = tid & 15;              // block-col

    // img (B,C,128,128): plane stride 16384 floats, row stride 128
    const float* src = img + ((size_t)bc << 14) + (size_t)nh * 1024 + (size_t)nw * 8;

    // ---- 2D DCT, butterfly both passes, zigzag-renamed accumulators
    float Yz[64];
#pragma unroll
    for (int p = 0; p < 64; ++p) Yz[p] = 0.f;

#pragma unroll
    for (int rp = 0; rp < 4; ++rp) {       // row pair (rp, 7-rp)
        float Ta[8], Tb[8];
        row_dct(src + rp * 128,       Ta);
        row_dct(src + (7 - rp) * 128, Tb);
#pragma unroll
        for (int j = 0; j < 8; ++j) {
            float s = Ta[j] + Tb[j];       // feeds even output rows
            float d = Ta[j] - Tb[j];       // feeds odd output rows
#pragma unroll
            for (int h = 0; h < 4; ++h) {
                Yz[INVZ[(2*h)    *8 + j]] = fmaf(s, DCm[2*h][rp],     Yz[INVZ[(2*h)    *8 + j]]);
                Yz[INVZ[(2*h + 1)*8 + j]] = fmaf(d, DCm[2*h + 1][rp], Yz[INVZ[(2*h + 1)*8 + j]]);
            }
        }
    }
    // fold the (x - 128) bias: only the DC coefficient is affected
    Yz[0] -= 1024.0f;                      // INVZ[0] == 0

    // ---- stage (zigzag-ordered): 16 conflict-free STS.128
    float* st = stage + tid * STRIDE;
#pragma unroll
    for (int k = 0; k < 16; ++k)
        *(float4*)(st + 4 * k) =
            make_float4(Yz[4*k], Yz[4*k + 1], Yz[4*k + 2], Yz[4*k + 3]);
    __syncthreads();

    // ---- coalesced writes: 16 regions of 2KB (one per nw), both tensors
    const size_t obase = (size_t)nh * (16 * 98304) + (size_t)bcg * 512 + tid * 4;
    const int slotbase = (tid >> 4) * 16;      // stage slot = bcl*16 + it
    const int pos      = (tid & 15) * 4;       // zigzag pos within block
    const float4 qv    = *(const float4*)(Qinv + pos);
#pragma unroll
    for (int it = 0; it < 16; ++it) {
        float4 v = *(const float4*)(stage + (slotbase + it) * STRIDE + pos);
        float4 q = make_float4(rintf(v.x * qv.x), rintf(v.y * qv.y),
                               rintf(v.z * qv.z), rintf(v.w * qv.w));
        const size_t o = obase + (size_t)it * 98304;
        *(float4*)(out_nq + o) = v;
        *(float4*)(out_q  + o) = q;
    }
}

extern "C" void kernel_launch(void* const* d_in, const int* in_sizes, int n_in,
                              void* d_out, int out_size)
{
    const float* img = (const float*)d_in[0];   // (512,3,128,128) fp32
    const float* Qm  = (const float*)d_in[2];   // (8,8) fp32
    float* out = (float*)d_out;

    const size_t half = (size_t)out_size / 2;   // flatten | no_quan_flatten
    jpeg_encode_kernel<<<3072, BT>>>(img, Qm, out, out + half);
}

// round 17
// speedup vs baseline: 1.0280x; 1.0155x over previous
#include <cuda_runtime.h>

// JPEG encode: (512,3,128,128) fp32 -> -128 -> 8x8 DCT -> quant -> zigzag
// out = [flatten (256,512,192) | no_quan_flatten (256,512,192)] fp32
//
// FINAL (best measured: dur 51.94us, kernel 46.0us; reconfirmed x4):
//  - CTA = (block-row nh, group of 8 planes); half-warp sweeps a contiguous
//    512B image row -> near-ideal read coalescing for 8x8-block access
//  - butterfly 8-pt DCT both passes, coefficients baked as FFMA immediates
//  - (x-128) bias folded into the DC coefficient (exact for AC terms)
//  - zigzag via compile-time register renaming (free)
//  - one-pass smem stage (stride-68 slots, conflict-free 16B ld/st), then
//    fully-coalesced float4 stores of both output tensors
//  - launch_bounds(128,5): 96 regs preserves per-warp LDG batching (MLP)
// Steady-state: 302MB/iter / 46.0us = 6.56TB/s = ~82% of spec = HBM roofline.
// Neutral probes: __ldcs/__stcs, cp.async, __ldcg, L2::evict_last+LDG.256.
// Regressed probes: 2-tile CTA, 2-pass stage, reg caps (MLP loss / spill).
// Rejected on cycle model: BT=192/256 (reg-file cuts threads/SM), shfl
// transpose (~256 SHFL/thread vs 32 conflict-free LDS/STS).

#define BT 128
#define STRIDE 68   // floats; 272B slot pitch -> conflict-free 16B ld/st

// 0.5*cos(k*pi/16)
#define C1f 0.49039264020161522f
#define C2f 0.46193976625564338f
#define C3f 0.41573480615127262f
#define C4f 0.35355339059327376f
#define C5f 0.27778511650980111f
#define C6f 0.19134171618254489f
#define C7f 0.09754516100806413f

// D[j][k] for k=0..3 (k=4..7 follow by even/odd symmetry)
__device__ constexpr float DCm[8][4] = {
    { C4f,  C4f,  C4f,  C4f},
    { C1f,  C3f,  C5f,  C7f},
    { C2f,  C6f, -C6f, -C2f},
    { C3f, -C7f, -C1f, -C5f},
    { C4f, -C4f, -C4f,  C4f},
    { C5f, -C1f,  C7f,  C3f},
    { C6f, -C2f,  C2f, -C6f},
    { C7f, -C5f,  C3f, -C1f}};

__constant__ int c_zz[64] = {  // zigzag position p reads flat index zz[p]
     0,  1,  8, 16,  9,  2,  3, 10,
    17, 24, 32, 25, 18, 11,  4,  5,
    12, 19, 26, 33, 40, 48, 41, 34,
    27, 20, 13,  6,  7, 14, 21, 28,
    35, 42, 49, 56, 57, 50, 43, 36,
    29, 22, 15, 23, 30, 37, 44, 51,
    58, 59, 52, 45, 38, 31, 39, 46,
    53, 60, 61, 54, 47, 55, 62, 63};

// inverse zigzag: flat (i*8+j) lands at zigzag position INVZ[i*8+j]
__device__ constexpr int INVZ[64] = {
     0,  1,  5,  6, 14, 15, 27, 28,
     2,  4,  7, 13, 16, 26, 29, 42,
     3,  8, 12, 17, 25, 30, 41, 43,
     9, 11, 18, 24, 31, 40, 44, 53,
    10, 19, 23, 32, 39, 45, 52, 54,
    20, 22, 33, 38, 46, 51, 55, 60,
    21, 34, 37, 47, 50, 56, 59, 61,
    35, 36, 48, 49, 57, 58, 62, 63};

// Row DCT of one image row via even/odd butterfly
__device__ __forceinline__ void row_dct(const float* __restrict__ rsrc, float T[8])
{
    float4 a = *(const float4*)rsrc;
    float4 b = *(const float4*)(rsrc + 4);
    float e0 = a.x + b.w, e1 = a.y + b.z, e2 = a.z + b.y, e3 = a.w + b.x;
    float o0 = a.x - b.w, o1 = a.y - b.z, o2 = a.z - b.y, o3 = a.w - b.x;
#pragma unroll
    for (int j = 0; j < 8; j += 2) {
        T[j]   = fmaf(e3, DCm[j][3],   fmaf(e2, DCm[j][2],   fmaf(e1, DCm[j][1],   e0 * DCm[j][0])));
        T[j+1] = fmaf(o3, DCm[j+1][3], fmaf(o2, DCm[j+1][2], fmaf(o1, DCm[j+1][1], o0 * DCm[j+1][0])));
    }
}

__global__ __launch_bounds__(BT, 5)
void jpeg_encode_kernel(const float* __restrict__ img,
                        const float* __restrict__ Qm,
                        float* __restrict__ out_q,
                        float* __restrict__ out_nq)
{
    __shared__ float Qinv[64];             // 1/Q in zigzag order
    __shared__ float stage[BT * STRIDE];   // full stage: one slot per thread

    const int tid = threadIdx.x;
    if (tid < 64) Qinv[tid] = 1.0f / Qm[c_zz[tid]];

    // CTA = (nh, group of 8 planes); thread = (plane-in-group, nw)
    const int bid = blockIdx.x;            // 0..3071
    const int nh  = bid / 192;             // block-row 0..15
    const int bcg = bid % 192;             // plane group (8 planes each)
    const int bc  = bcg * 8 + (tid >> 4);  // plane = b*3+c
    const int nw  = tid & 15;              // block-col

    // img (B,C,128,128): plane stride 16384 floats, row stride 128
    const float* src = img + ((size_t)bc << 14) + (size_t)nh * 1024 + (size_t)nw * 8;

    // ---- 2D DCT, butterfly both passes, zigzag-renamed accumulators
    float Yz[64];
#pragma unroll
    for (int p = 0; p < 64; ++p) Yz[p] = 0.f;

#pragma unroll
    for (int rp = 0; rp < 4; ++rp) {       // row pair (rp, 7-rp)
        float Ta[8], Tb[8];
        row_dct(src + rp * 128,       Ta);
        row_dct(src + (7 - rp) * 128, Tb);
#pragma unroll
        for (int j = 0; j < 8; ++j) {
            float s = Ta[j] + Tb[j];       // feeds even output rows
            float d = Ta[j] - Tb[j];       // feeds odd output rows
#pragma unroll
            for (int h = 0; h < 4; ++h) {
                Yz[INVZ[(2*h)    *8 + j]] = fmaf(s, DCm[2*h][rp],     Yz[INVZ[(2*h)    *8 + j]]);
                Yz[INVZ[(2*h + 1)*8 + j]] = fmaf(d, DCm[2*h + 1][rp], Yz[INVZ[(2*h + 1)*8 + j]]);
            }
        }
    }
    // fold the (x - 128) bias: only the DC coefficient is affected
    Yz[0] -= 1024.0f;                      // INVZ[0] == 0

    // ---- stage (zigzag-ordered): 16 conflict-free STS.128
    float* st = stage + tid * STRIDE;
#pragma unroll
    for (int k = 0; k < 16; ++k)
        *(float4*)(st + 4 * k) =
            make_float4(Yz[4*k], Yz[4*k + 1], Yz[4*k + 2], Yz[4*k + 3]);
    __syncthreads();

    // ---- coalesced writes: 16 regions of 2KB (one per nw), both tensors
    const size_t obase = (size_t)nh * (16 * 98304) + (size_t)bcg * 512 + tid * 4;
    const int slotbase = (tid >> 4) * 16;      // stage slot = bcl*16 + it
    const int pos      = (tid & 15) * 4;       // zigzag pos within block
    const float4 qv    = *(const float4*)(Qinv + pos);
#pragma unroll
    for (int it = 0; it < 16; ++it) {
        float4 v = *(const float4*)(stage + (slotbase + it) * STRIDE + pos);
        float4 q = make_float4(rintf(v.x * qv.x), rintf(v.y * qv.y),
                               rintf(v.z * qv.z), rintf(v.w * qv.w));
        const size_t o = obase + (size_t)it * 98304;
        *(float4*)(out_nq + o) = v;
        *(float4*)(out_q  + o) = q;
    }
}

extern "C" void kernel_launch(void* const* d_in, const int* in_sizes, int n_in,
                              void* d_out, int out_size)
{
    const float* img = (const float*)d_in[0];   // (512,3,128,128) fp32
    const float* Qm  = (const float*)d_in[2];   // (8,8) fp32
    float* out = (float*)d_out;

    const size_t half = (size_t)out_size / 2;   // flatten | no_quan_flatten
    jpeg_encode_kernel<<<3072, BT>>>(img, Qm, out, out + half);
}